// round 15
// baseline (speedup 1.0000x reference)
#include <cuda_runtime.h>
#include <cuda_bf16.h>
#include <math.h>
#include <stdint.h>

#define BB      32
#define TSLEN   256
#define DD      256
#define FF      256
#define MAXMEL  2048
#define NBINS   256

#define OUT_ELEMS   (BB*MAXMEL*2*DD)
#define LOGDUR_OFF  OUT_ELEMS
#define PITCH_OFF   (LOGDUR_OFF + BB*TSLEN)
#define MEL_OFF     (PITCH_OFF + BB*MAXMEL)

#define WCONV (256*768)
#define WPROJ (512*256)
#define PROWS (BB*MAXMEL)
#define DROWS (BB*TSLEN)

typedef __nv_bfloat16 bf16;

// ---------------- scratch -------------------------------------------------------
__device__ __align__(128) float g_bufA[PROWS*FF];
__device__ __align__(128) float g_bufB[DROWS*FF];
__device__ __align__(128) bf16  g_xh[PROWS*DD];
__device__ __align__(128) bf16  g_xl[PROWS*DD];
__device__ __align__(128) bf16  g_yh[PROWS*FF];
__device__ __align__(128) bf16  g_yl[PROWS*FF];
__device__ __align__(128) bf16  g_dh[DROWS*DD];
__device__ __align__(128) bf16  g_dl[DROWS*DD];
__device__ __align__(128) bf16  g_wh[4*WCONV + WPROJ];
__device__ __align__(128) bf16  g_wl[4*WCONV + WPROJ];
__device__ int g_idx[PROWS];
__device__ int g_mellen[BB];

// ---------------- helpers -------------------------------------------------------
__device__ __forceinline__ void cpa16(uint32_t d, const void* s, int sz) {
    asm volatile("cp.async.cg.shared.global [%0], [%1], 16, %2;" :: "r"(d), "l"(s), "r"(sz));
}
__device__ __forceinline__ void ldm4(uint32_t* r, uint32_t a) {
    asm volatile("ldmatrix.sync.aligned.m8n8.x4.shared.b16 {%0,%1,%2,%3}, [%4];"
        : "=r"(r[0]), "=r"(r[1]), "=r"(r[2]), "=r"(r[3]) : "r"(a));
}
__device__ __forceinline__ void mma16816(float* c, const uint32_t* a, uint32_t b0, uint32_t b1) {
    asm volatile(
        "mma.sync.aligned.m16n8k16.row.col.f32.bf16.bf16.f32 "
        "{%0,%1,%2,%3}, {%4,%5,%6,%7}, {%8,%9}, {%0,%1,%2,%3};"
        : "+f"(c[0]), "+f"(c[1]), "+f"(c[2]), "+f"(c[3])
        : "r"(a[0]), "r"(a[1]), "r"(a[2]), "r"(a[3]), "r"(b0), "r"(b1));
}
__device__ __forceinline__ void split1(float x, bf16& h, bf16& l) {
    h = __float2bfloat16_rn(x);
    l = __float2bfloat16_rn(x - __bfloat162float(h));
}
__device__ __forceinline__ float wredsum(float v) {
    #pragma unroll
    for (int o = 16; o; o >>= 1) v += __shfl_xor_sync(0xffffffffu, v, o);
    return v;
}
__device__ __forceinline__ void split8(const float* y, uint4& hv, uint4& lv) {
    uint32_t* hp = (uint32_t*)&hv;
    uint32_t* lp = (uint32_t*)&lv;
    #pragma unroll
    for (int i = 0; i < 4; i++) {
        bf16 h0, l0, h1, l1;
        split1(y[2*i],   h0, l0);
        split1(y[2*i+1], h1, l1);
        hp[i] = (uint32_t)__bfloat16_as_ushort(h0) | ((uint32_t)__bfloat16_as_ushort(h1) << 16);
        lp[i] = (uint32_t)__bfloat16_as_ushort(l0) | ((uint32_t)__bfloat16_as_ushort(l1) << 16);
    }
}
__device__ __forceinline__ void ld8(const float* p, float* y) {
    float4 a = *(const float4*)(p);
    float4 b = *(const float4*)(p + 4);
    y[0]=a.x; y[1]=a.y; y[2]=a.z; y[3]=a.w; y[4]=b.x; y[5]=b.y; y[6]=b.z; y[7]=b.w;
}

// 3-stage swizzled SMEM
#define T3 8192
#define SM_TOTAL3 (12*T3)
__device__ __forceinline__ uint32_t swst(int row, int kc) {
    return (uint32_t)(row*64 + ((kc ^ ((row>>1)&3)) << 4));
}

// ---------------- GEMM core (R13/R14, unchanged) -----------------------------------
template<int KWIN, bool RELU, bool MASK>
__device__ __forceinline__ void gemm_core(
    const bf16* __restrict__ Ahi, const bf16* __restrict__ Alo,
    const bf16* __restrict__ Whi, const bf16* __restrict__ Wlo,
    const float* __restrict__ bias, float* __restrict__ Y, int Cout,
    int row0, int n0, int tmask, const int* __restrict__ mellen,
    int skipmode, uint32_t sb)
{
    constexpr int NS = KWIN * 8;
    constexpr int K  = KWIN * 256;
    const int tid = threadIdx.x;
    const int wid = tid >> 5, lid = tid & 31;
    const int wm = wid >> 1, wn = wid & 1;
    const int tloc0 = row0 & tmask;
    const int gseg  = row0 - tloc0;
    const int Tb    = tmask + 1;

    int mlv = 0;
    if (MASK || skipmode) mlv = mellen[(uint32_t)row0 / (uint32_t)Tb];
    if (skipmode == 1 && tloc0 > mlv)  return;
    if (skipmode == 2 && tloc0 >= mlv) return;
    const bool zerotile = MASK && (tloc0 >= mlv);

    int rowA[4], swA[4];
    #pragma unroll
    for (int mt = 0; mt < 4; mt++) {
        rowA[mt] = wm*64 + mt*16 + (lid & 15);
        swA[mt]  = (rowA[mt] >> 1) & 3;
    }
    const int hA = (lid >> 4) & 1;
    int rowB[4], swB[4];
    #pragma unroll
    for (int p = 0; p < 4; p++) {
        rowB[p] = wn*64 + p*16 + (lid & 7) + ((lid & 16) >> 1);
        swB[p]  = (rowB[p] >> 1) & 3;
    }
    const int hB = (lid >> 3) & 1;

    float acc[4][8][4];
    #pragma unroll
    for (int i = 0; i < 4; i++)
        #pragma unroll
        for (int j = 0; j < 8; j++)
            #pragma unroll
            for (int e = 0; e < 4; e++) acc[i][j][e] = 0.f;

    auto load_stage = [&](int s, int st) {
        const int tap = (KWIN == 3) ? (s >> 3) : 0;
        const int cb  = (s & 7) * 32;
        #pragma unroll
        for (int h2 = 0; h2 < 4; h2++) {
            const int c = tid + h2*128;
            const int row = c >> 2, kc = c & 3;
            const int src = tloc0 + row + tap - (KWIN >> 1);
            const bool valid = (KWIN == 1) || (src >= 0 && src < Tb);
            const size_t go = (size_t)(gseg + (valid ? src : 0))*256 + cb + kc*8;
            const uint32_t d = swst(row, kc);
            cpa16(sb + st*T3     + d, Ahi + go, valid ? 16 : 0);
            cpa16(sb + (3+st)*T3 + d, Alo + go, valid ? 16 : 0);
        }
        #pragma unroll
        for (int h2 = 0; h2 < 4; h2++) {
            const int c = tid + h2*128;
            const int row = c >> 2, kc = c & 3;
            const size_t go = (size_t)(n0 + row)*K + s*32 + kc*8;
            const uint32_t d = swst(row, kc);
            cpa16(sb + (6+st)*T3 + d, Whi + go, 16);
            cpa16(sb + (9+st)*T3 + d, Wlo + go, 16);
        }
        asm volatile("cp.async.commit_group;");
    };

    auto compute_stage = [&](int st) {
        const uint32_t aHi = sb + st*T3,     aLo = sb + (3+st)*T3;
        const uint32_t bHi = sb + (6+st)*T3, bLo = sb + (9+st)*T3;
        #pragma unroll
        for (int q = 0; q < 2; q++) {
            uint32_t ah[4][4], al[4][4], bh[4][4], bl[4][4];
            #pragma unroll
            for (int mt = 0; mt < 4; mt++) {
                const uint32_t oA = (uint32_t)(rowA[mt]*64 + (((2*q + hA) ^ swA[mt]) << 4));
                ldm4(ah[mt], aHi + oA);
                ldm4(al[mt], aLo + oA);
            }
            #pragma unroll
            for (int p = 0; p < 4; p++) {
                const uint32_t oB = (uint32_t)(rowB[p]*64 + (((2*q + hB) ^ swB[p]) << 4));
                ldm4(bh[p], bHi + oB);
                ldm4(bl[p], bLo + oB);
            }
            #pragma unroll
            for (int mt = 0; mt < 4; mt++)
                #pragma unroll
                for (int p = 0; p < 4; p++) {
                    mma16816(acc[mt][2*p],   ah[mt], bh[p][0], bh[p][1]);
                    mma16816(acc[mt][2*p+1], ah[mt], bh[p][2], bh[p][3]);
                }
            #pragma unroll
            for (int mt = 0; mt < 4; mt++)
                #pragma unroll
                for (int p = 0; p < 4; p++) {
                    mma16816(acc[mt][2*p],   al[mt], bh[p][0], bh[p][1]);
                    mma16816(acc[mt][2*p+1], al[mt], bh[p][2], bh[p][3]);
                }
            #pragma unroll
            for (int mt = 0; mt < 4; mt++)
                #pragma unroll
                for (int p = 0; p < 4; p++) {
                    mma16816(acc[mt][2*p],   ah[mt], bl[p][0], bl[p][1]);
                    mma16816(acc[mt][2*p+1], ah[mt], bl[p][2], bl[p][3]);
                }
        }
    };

    if (!zerotile) {
        load_stage(0, 0);
        load_stage(1, 1);
        int stc = 0, stl = 2;
        #pragma unroll 1
        for (int s = 0; s < NS; s++) {
            if (s + 1 < NS) { asm volatile("cp.async.wait_group 1;"); }
            else            { asm volatile("cp.async.wait_group 0;"); }
            __syncthreads();
            if (s + 2 < NS) load_stage(s + 2, stl);
            compute_stage(stc);
            stc = (stc == 2) ? 0 : stc + 1;
            stl = (stl == 2) ? 0 : stl + 1;
        }
    }

    #pragma unroll
    for (int mt = 0; mt < 4; mt++) {
        const int r = row0 + wm*64 + mt*16 + (lid >> 2);
        const bool m0 = MASK && ((r     & tmask) >= mlv);
        const bool m1 = MASK && (((r+8) & tmask) >= mlv);
        #pragma unroll
        for (int nt = 0; nt < 8; nt++) {
            const int c = n0 + wn*64 + nt*8 + (lid & 3)*2;
            const float bb0 = bias[c], bb1 = bias[c+1];
            float v0 = acc[mt][nt][0] + bb0, v1 = acc[mt][nt][1] + bb1;
            float v2 = acc[mt][nt][2] + bb0, v3 = acc[mt][nt][3] + bb1;
            if (RELU) { v0 = fmaxf(v0,0.f); v1 = fmaxf(v1,0.f); v2 = fmaxf(v2,0.f); v3 = fmaxf(v3,0.f); }
            if (m0) { v0 = 0.f; v1 = 0.f; }
            if (m1) { v2 = 0.f; v3 = 0.f; }
            *(float2*)(Y + (size_t)r*Cout + c)     = make_float2(v0, v1);
            *(float2*)(Y + (size_t)(r+8)*Cout + c) = make_float2(v2, v3);
        }
    }
}

// ---------------- GEMM kernels ---------------------------------------------------
__global__ __launch_bounds__(128, 2)
void gemm_dual(const bf16* Ah0, const bf16* Al0, const bf16* Wh0, const bf16* Wl0,
               const float* b0, float* Y0, int tm0, int skip0,
               const bf16* Ah1, const bf16* Al1, const bf16* Wh1, const bf16* Wl1,
               const float* b1, float* Y1, int tm1,
               const int* mellen, int PB) {
    extern __shared__ char smc[];
    const uint32_t sb = (uint32_t)__cvta_generic_to_shared(smc);
    const int bx = blockIdx.x;
    const int n0 = blockIdx.y * 128;
    if (bx < PB) {
        gemm_core<3,true,false>(Ah0, Al0, Wh0, Wl0, b0, Y0, 256, bx*128, n0, tm0,
                                mellen, skip0, sb);
    } else {
        gemm_core<3,true,false>(Ah1, Al1, Wh1, Wl1, b1, Y1, 256, (bx-PB)*128, n0, tm1,
                                nullptr, 0, sb);
    }
}

__global__ __launch_bounds__(128, 2)
void gemm_proj(const bf16* Ah, const bf16* Al, const bf16* Wh, const bf16* Wl,
               const float* b, float* Y, const int* mellen) {
    extern __shared__ char smc[];
    const uint32_t sb = (uint32_t)__cvta_generic_to_shared(smc);
    gemm_core<1,false,true>(Ah, Al, Wh, Wl, b, Y, 512,
                            blockIdx.x*128, blockIdx.y*128, 2047, mellen, 0, sb);
}

// ---------------- weight prep + length regulator (merged) -------------------------
__global__ void prep_len(const float* __restrict__ dp_w1, const float* __restrict__ dp_w2,
                         const float* __restrict__ pp_w1, const float* __restrict__ pp_w2,
                         const float* __restrict__ proj_w,
                         bf16* __restrict__ H, bf16* __restrict__ L,
                         const int* __restrict__ dur, int* __restrict__ idxb,
                         int* __restrict__ mellen, float* __restrict__ out_mel) {
    int bid = blockIdx.x;
    if (bid < 3072) {
        int slot = bid / 768;
        const float* W = (slot == 0) ? dp_w1 : (slot == 1) ? dp_w2 : (slot == 2) ? pp_w1 : pp_w2;
        int o = (bid - slot*768) * 256 + threadIdx.x;
        int f = o / 768;
        int r = o - f * 768;
        int tap = r >> 8;
        int c = r & 255;
        float w = W[f*768 + c*3 + tap];
        bf16 h, l; split1(w, h, l);
        H[slot*WCONV + o] = h; L[slot*WCONV + o] = l;
    } else if (bid < 3584) {
        int o = (bid - 3072) * 256 + threadIdx.x;
        int n = o >> 8;
        int k = o & 255;
        float w = proj_w[k*512 + n];
        bf16 h, l; split1(w, h, l);
        H[4*WCONV + o] = h; L[4*WCONV + o] = l;
    } else {
        __shared__ int cum[TSLEN];
        int b = bid - 3584;
        int t = threadIdx.x;
        cum[t] = dur[b*TSLEN + t];
        __syncthreads();
        for (int off = 1; off < TSLEN; off <<= 1) {
            int v = (t >= off) ? cum[t - off] : 0;
            __syncthreads();
            cum[t] += v;
            __syncthreads();
        }
        int ml = min(cum[TSLEN-1], MAXMEL);
        if (t == 0) { mellen[b] = ml; out_mel[b] = (float)ml; }
        for (int m = t; m < MAXMEL; m += TSLEN) {
            int lo = 0, hi = TSLEN;
            while (lo < hi) { int mid = (lo + hi) >> 1; if (cum[mid] <= m) lo = mid + 1; else hi = mid; }
            idxb[b*MAXMEL + m] = min(lo, TSLEN - 1);
        }
    }
}

// ---------------- gather (pitch) + split (duration) -------------------------------
// Pitch rows with m > ml+128 are never read by valid conv1 tiles -> skip.
__global__ __launch_bounds__(256)
void gather_split(const float* __restrict__ ling, const int* __restrict__ idxb,
                  const int* __restrict__ mellen,
                  bf16* __restrict__ dh, bf16* __restrict__ dl) {
    int bx = blockIdx.x;
    const int lane = threadIdx.x & 31;
    const int c0 = lane*8;
    if (bx < PROWS/8) {
        int row = bx*8 + (threadIdx.x >> 5);
        int b = row >> 11;
        int m = row & (MAXMEL - 1);
        int ml = mellen[b];
        if (m > ml + 128) return;              // never read by valid tiles
        bool masked = (m >= ml);
        int src = idxb[row];
        float y[8] = {0,0,0,0,0,0,0,0};
        if (!masked) ld8(ling + ((size_t)b*TSLEN + src)*DD + c0, y);
        uint4 hv, lv;
        split8(y, hv, lv);
        *(uint4*)(g_xh + (size_t)row*DD + c0) = hv;
        *(uint4*)(g_xl + (size_t)row*DD + c0) = lv;
    } else {
        int row = (bx - PROWS/8)*8 + (threadIdx.x >> 5);
        float y[8];
        ld8(ling + (size_t)row*DD + c0, y);
        uint4 hv, lv;
        split8(y, hv, lv);
        *(uint4*)(dh + (size_t)row*DD + c0) = hv;
        *(uint4*)(dl + (size_t)row*DD + c0) = lv;
    }
}

// ---------------- LayerNorm + split: warp per row ----------------------------------
// Pitch rows with m > ml+127 are never read by valid conv2 tiles -> skip.
__global__ __launch_bounds__(256)
void ln_dual(const float* __restrict__ H0, const float* __restrict__ g0,
             const float* __restrict__ be0, bf16* __restrict__ hi0, bf16* __restrict__ lo0,
             int R0, const int* __restrict__ mellen,
             const float* __restrict__ H1, const float* __restrict__ g1,
             const float* __restrict__ be1, bf16* __restrict__ hi1, bf16* __restrict__ lo1) {
    const int gr = blockIdx.x*8 + (threadIdx.x >> 5);
    const int lane = threadIdx.x & 31;
    const float *H, *g, *be;
    bf16 *hi, *lo;
    int row;
    if (gr < R0) {
        H = H0; g = g0; be = be0; hi = hi0; lo = lo0; row = gr;
        const int m = row & (MAXMEL - 1);
        if (m > mellen[row >> 11] + 127) return;
    } else {
        H = H1; g = g1; be = be1; hi = hi1; lo = lo1; row = gr - R0;
    }
    const int c0 = lane*8;
    float x[8], gg[8], bb[8];
    ld8(H + (size_t)row*FF + c0, x);
    ld8(g + c0, gg);
    ld8(be + c0, bb);
    float s1 = 0.f, s2 = 0.f;
    #pragma unroll
    for (int i = 0; i < 8; i++) { s1 += x[i]; s2 += x[i]*x[i]; }
    s1 = wredsum(s1);
    s2 = wredsum(s2);
    float mean = s1 * (1.f/256.f);
    float var  = s2 * (1.f/256.f) - mean*mean;
    float rstd = rsqrtf(var + 1e-5f);
    float y[8];
    #pragma unroll
    for (int i = 0; i < 8; i++)
        y[i] = (x[i] - mean) * rstd * gg[i] + bb[i];
    uint4 hv, lv;
    split8(y, hv, lv);
    *(uint4*)(hi + (size_t)row*FF + c0) = hv;
    *(uint4*)(lo + (size_t)row*FF + c0) = lv;
}

// ---------------- heads: warp per row -----------------------------------------------
// Masked pitch rows: only pout=0 needed (their xh/xl rows feed masked proj outputs).
__global__ __launch_bounds__(256)
void heads_dual(const float* __restrict__ Hp, const float* __restrict__ gp,
                const float* __restrict__ bep, const float* __restrict__ lwp,
                const float* __restrict__ lbp, const float* __restrict__ bins,
                const float* __restrict__ emb, const int* __restrict__ mellen,
                const float* __restrict__ ling, const int* __restrict__ idxb,
                float* __restrict__ pout,
                const float* __restrict__ Hd, const float* __restrict__ gd,
                const float* __restrict__ bed, const float* __restrict__ lwd,
                const float* __restrict__ lbd, float* __restrict__ dout) {
    const int gr = blockIdx.x*8 + (threadIdx.x >> 5);
    const int lane = threadIdx.x & 31;
    const bool isPitch = (gr < PROWS);
    const int row = isPitch ? gr : gr - PROWS;

    if (isPitch) {
        const int b = row >> 11;
        const int m = row & (MAXMEL - 1);
        if (m >= mellen[b]) {                  // masked: pout=0, nothing else needed
            if (lane == 0) pout[row] = 0.f;
            return;
        }
    }

    const float* H  = isPitch ? Hp  : Hd;
    const float* g  = isPitch ? gp  : gd;
    const float* be = isPitch ? bep : bed;
    const float* lw = isPitch ? lwp : lwd;
    const float* lb = isPitch ? lbp : lbd;

    const int c0 = lane*8;
    float x[8], gg[8], bb[8], ww[8];
    ld8(H + (size_t)row*FF + c0, x);
    ld8(g + c0, gg);
    ld8(be + c0, bb);
    ld8(lw + c0, ww);
    float s1 = 0.f, s2 = 0.f;
    #pragma unroll
    for (int i = 0; i < 8; i++) { s1 += x[i]; s2 += x[i]*x[i]; }
    s1 = wredsum(s1);
    s2 = wredsum(s2);
    float mean = s1 * (1.f/256.f);
    float var  = s2 * (1.f/256.f) - mean*mean;
    float rstd = rsqrtf(var + 1e-5f);
    float dot = 0.f;
    #pragma unroll
    for (int i = 0; i < 8; i++)
        dot += ((x[i] - mean) * rstd * gg[i] + bb[i]) * ww[i];
    dot = wredsum(dot);
    float a = dot + lb[0];

    if (isPitch) {
        const int b = row >> 11;
        if (lane == 0) pout[row] = a;
        int lo = 0, hi = NBINS - 1;
        while (lo < hi) { int mid = (lo + hi) >> 1; if (bins[mid] < a) lo = mid + 1; else hi = mid; }
        const int bkt = lo;
        const int src = idxb[row];
        float ev[8], bv[8];
        ld8(emb + (size_t)bkt*DD + c0, ev);
        ld8(ling + ((size_t)b*TSLEN + src)*DD + c0, bv);
        float xv[8];
        #pragma unroll
        for (int i = 0; i < 8; i++) xv[i] = bv[i] + ev[i];
        uint4 hv, lv;
        split8(xv, hv, lv);
        *(uint4*)(g_xh + (size_t)row*DD + c0) = hv;
        *(uint4*)(g_xl + (size_t)row*DD + c0) = lv;
    } else {
        if (lane == 0) dout[row] = a;
    }
}

// ------------------------------- launch ------------------------------------------
extern "C" void kernel_launch(void* const* d_in, const int* in_sizes, int n_in,
                              void* d_out, int out_size) {
    const float* ling   = (const float*)d_in[0];
    const int*   dur    = (const int*)  d_in[1];
    const float* dp_w1  = (const float*)d_in[3];
    const float* dp_b1  = (const float*)d_in[4];
    const float* dp_g1  = (const float*)d_in[5];
    const float* dp_be1 = (const float*)d_in[6];
    const float* dp_w2  = (const float*)d_in[7];
    const float* dp_b2  = (const float*)d_in[8];
    const float* dp_g2  = (const float*)d_in[9];
    const float* dp_be2 = (const float*)d_in[10];
    const float* dp_lw  = (const float*)d_in[11];
    const float* dp_lb  = (const float*)d_in[12];
    const float* pp_w1  = (const float*)d_in[13];
    const float* pp_b1  = (const float*)d_in[14];
    const float* pp_g1  = (const float*)d_in[15];
    const float* pp_be1 = (const float*)d_in[16];
    const float* pp_w2  = (const float*)d_in[17];
    const float* pp_b2  = (const float*)d_in[18];
    const float* pp_g2  = (const float*)d_in[19];
    const float* pp_be2 = (const float*)d_in[20];
    const float* pp_lw  = (const float*)d_in[21];
    const float* pp_lb  = (const float*)d_in[22];
    const float* bins   = (const float*)d_in[23];
    const float* emb    = (const float*)d_in[24];
    const float* proj_w = (const float*)d_in[25];
    const float* proj_b = (const float*)d_in[26];

    float* out = (float*)d_out;

    float *bufA, *bufB;
    bf16 *wh, *wl, *xh, *xl, *yh, *yl, *dh, *dl;
    int *idxb, *mellen;
    cudaGetSymbolAddress((void**)&bufA,   g_bufA);
    cudaGetSymbolAddress((void**)&bufB,   g_bufB);
    cudaGetSymbolAddress((void**)&wh,     g_wh);
    cudaGetSymbolAddress((void**)&wl,     g_wl);
    cudaGetSymbolAddress((void**)&xh,     g_xh);
    cudaGetSymbolAddress((void**)&xl,     g_xl);
    cudaGetSymbolAddress((void**)&yh,     g_yh);
    cudaGetSymbolAddress((void**)&yl,     g_yl);
    cudaGetSymbolAddress((void**)&dh,     g_dh);
    cudaGetSymbolAddress((void**)&dl,     g_dl);
    cudaGetSymbolAddress((void**)&idxb,   g_idx);
    cudaGetSymbolAddress((void**)&mellen, g_mellen);

    cudaFuncSetAttribute(gemm_dual, cudaFuncAttributeMaxDynamicSharedMemorySize, SM_TOTAL3);
    cudaFuncSetAttribute(gemm_proj, cudaFuncAttributeMaxDynamicSharedMemorySize, SM_TOTAL3);

    // 1: weight prep + length regulator (merged)
    prep_len<<<3584 + BB, 256>>>(dp_w1, dp_w2, pp_w1, pp_w2, proj_w, wh, wl,
                                 dur, idxb, mellen, out + MEL_OFF);
    // 2: gather (pitch, row-skip) + split (duration)
    gather_split<<<PROWS/8 + DROWS/8, 256>>>(ling, idxb, mellen, dh, dl);
    // 3: conv1 dual (skipmode 1)
    gemm_dual<<<dim3(512 + 64, 2), 128, SM_TOTAL3>>>(
        xh, xl, wh + 2*WCONV, wl + 2*WCONV, pp_b1, bufA, 2047, 1,
        dh, dl, wh + 0*WCONV, wl + 0*WCONV, dp_b1, bufB, 255, mellen, 512);
    // 4: LN dual (row-skip) <- ncu capture slot
    ln_dual<<<(PROWS + DROWS)/8, 256>>>(bufA, pp_g1, pp_be1, yh, yl, PROWS, mellen,
                                        bufB, dp_g1, dp_be1, dh, dl);
    // 5: conv2 dual (skipmode 2)
    gemm_dual<<<dim3(512 + 64, 2), 128, SM_TOTAL3>>>(
        yh, yl, wh + 3*WCONV, wl + 3*WCONV, pp_b2, bufA, 2047, 2,
        dh, dl, wh + 1*WCONV, wl + 1*WCONV, dp_b2, bufB, 255, mellen, 512);
    // 6: heads dual (masked-row early out)
    heads_dual<<<(PROWS + DROWS)/8, 256>>>(
        bufA, pp_g2, pp_be2, pp_lw, pp_lb, bins, emb, mellen, ling, idxb, out + PITCH_OFF,
        bufB, dp_g2, dp_be2, dp_lw, dp_lb, out + LOGDUR_OFF);
    // 7: final projection (masked; fully-masked tiles zero-store fast path)
    gemm_proj<<<dim3(512, 4), 128, SM_TOTAL3>>>(
        xh, xl, wh + 4*WCONV, wl + 4*WCONV, proj_b, out, mellen);
}

// round 16
// speedup vs baseline: 1.0077x; 1.0077x over previous
#include <cuda_runtime.h>
#include <cuda_bf16.h>
#include <math.h>
#include <stdint.h>

#define BB      32
#define TSLEN   256
#define DD      256
#define FF      256
#define MAXMEL  2048
#define NBINS   256

#define OUT_ELEMS   (BB*MAXMEL*2*DD)
#define LOGDUR_OFF  OUT_ELEMS
#define PITCH_OFF   (LOGDUR_OFF + BB*TSLEN)
#define MEL_OFF     (PITCH_OFF + BB*MAXMEL)

#define WCONV (256*768)
#define WPROJ (512*256)
#define PROWS (BB*MAXMEL)
#define DROWS (BB*TSLEN)

typedef __nv_bfloat16 bf16;

// ---------------- scratch -------------------------------------------------------
__device__ __align__(128) float g_bufA[PROWS*FF];
__device__ __align__(128) float g_bufB[DROWS*FF];
__device__ __align__(128) bf16  g_xh[PROWS*DD];
__device__ __align__(128) bf16  g_xl[PROWS*DD];
__device__ __align__(128) bf16  g_yh[PROWS*FF];
__device__ __align__(128) bf16  g_yl[PROWS*FF];
__device__ __align__(128) bf16  g_dh[DROWS*DD];
__device__ __align__(128) bf16  g_dl[DROWS*DD];
__device__ __align__(128) bf16  g_wh[4*WCONV + WPROJ];
__device__ __align__(128) bf16  g_wl[4*WCONV + WPROJ];
__device__ int g_idx[PROWS];
__device__ int g_mellen[BB];

// ---------------- helpers -------------------------------------------------------
__device__ __forceinline__ void cpa16(uint32_t d, const void* s, int sz) {
    asm volatile("cp.async.cg.shared.global [%0], [%1], 16, %2;" :: "r"(d), "l"(s), "r"(sz));
}
__device__ __forceinline__ void ldm4(uint32_t* r, uint32_t a) {
    asm volatile("ldmatrix.sync.aligned.m8n8.x4.shared.b16 {%0,%1,%2,%3}, [%4];"
        : "=r"(r[0]), "=r"(r[1]), "=r"(r[2]), "=r"(r[3]) : "r"(a));
}
__device__ __forceinline__ void mma16816(float* c, const uint32_t* a, uint32_t b0, uint32_t b1) {
    asm volatile(
        "mma.sync.aligned.m16n8k16.row.col.f32.bf16.bf16.f32 "
        "{%0,%1,%2,%3}, {%4,%5,%6,%7}, {%8,%9}, {%0,%1,%2,%3};"
        : "+f"(c[0]), "+f"(c[1]), "+f"(c[2]), "+f"(c[3])
        : "r"(a[0]), "r"(a[1]), "r"(a[2]), "r"(a[3]), "r"(b0), "r"(b1));
}
__device__ __forceinline__ void split1(float x, bf16& h, bf16& l) {
    h = __float2bfloat16_rn(x);
    l = __float2bfloat16_rn(x - __bfloat162float(h));
}
__device__ __forceinline__ float wredsum(float v) {
    #pragma unroll
    for (int o = 16; o; o >>= 1) v += __shfl_xor_sync(0xffffffffu, v, o);
    return v;
}
__device__ __forceinline__ void split8(const float* y, uint4& hv, uint4& lv) {
    uint32_t* hp = (uint32_t*)&hv;
    uint32_t* lp = (uint32_t*)&lv;
    #pragma unroll
    for (int i = 0; i < 4; i++) {
        bf16 h0, l0, h1, l1;
        split1(y[2*i],   h0, l0);
        split1(y[2*i+1], h1, l1);
        hp[i] = (uint32_t)__bfloat16_as_ushort(h0) | ((uint32_t)__bfloat16_as_ushort(h1) << 16);
        lp[i] = (uint32_t)__bfloat16_as_ushort(l0) | ((uint32_t)__bfloat16_as_ushort(l1) << 16);
    }
}
__device__ __forceinline__ void ld8(const float* p, float* y) {
    float4 a = *(const float4*)(p);
    float4 b = *(const float4*)(p + 4);
    y[0]=a.x; y[1]=a.y; y[2]=a.z; y[3]=a.w; y[4]=b.x; y[5]=b.y; y[6]=b.z; y[7]=b.w;
}

// 3-stage swizzled SMEM
#define T3 8192
#define SM_TOTAL3 (12*T3)
__device__ __forceinline__ uint32_t swst(int row, int kc) {
    return (uint32_t)(row*64 + ((kc ^ ((row>>1)&3)) << 4));
}

// ---------------- GEMM core (R13/R14, unchanged) -----------------------------------
template<int KWIN, bool RELU, bool MASK>
__device__ __forceinline__ void gemm_core(
    const bf16* __restrict__ Ahi, const bf16* __restrict__ Alo,
    const bf16* __restrict__ Whi, const bf16* __restrict__ Wlo,
    const float* __restrict__ bias, float* __restrict__ Y, int Cout,
    int row0, int n0, int tmask, const int* __restrict__ mellen,
    int skipmode, uint32_t sb)
{
    constexpr int NS = KWIN * 8;
    constexpr int K  = KWIN * 256;
    const int tid = threadIdx.x;
    const int wid = tid >> 5, lid = tid & 31;
    const int wm = wid >> 1, wn = wid & 1;
    const int tloc0 = row0 & tmask;
    const int gseg  = row0 - tloc0;
    const int Tb    = tmask + 1;

    int mlv = 0;
    if (MASK || skipmode) mlv = mellen[(uint32_t)row0 / (uint32_t)Tb];
    if (skipmode == 1 && tloc0 > mlv)  return;
    if (skipmode == 2 && tloc0 >= mlv) return;
    const bool zerotile = MASK && (tloc0 >= mlv);

    int rowA[4], swA[4];
    #pragma unroll
    for (int mt = 0; mt < 4; mt++) {
        rowA[mt] = wm*64 + mt*16 + (lid & 15);
        swA[mt]  = (rowA[mt] >> 1) & 3;
    }
    const int hA = (lid >> 4) & 1;
    int rowB[4], swB[4];
    #pragma unroll
    for (int p = 0; p < 4; p++) {
        rowB[p] = wn*64 + p*16 + (lid & 7) + ((lid & 16) >> 1);
        swB[p]  = (rowB[p] >> 1) & 3;
    }
    const int hB = (lid >> 3) & 1;

    float acc[4][8][4];
    #pragma unroll
    for (int i = 0; i < 4; i++)
        #pragma unroll
        for (int j = 0; j < 8; j++)
            #pragma unroll
            for (int e = 0; e < 4; e++) acc[i][j][e] = 0.f;

    auto load_stage = [&](int s, int st) {
        const int tap = (KWIN == 3) ? (s >> 3) : 0;
        const int cb  = (s & 7) * 32;
        #pragma unroll
        for (int h2 = 0; h2 < 4; h2++) {
            const int c = tid + h2*128;
            const int row = c >> 2, kc = c & 3;
            const int src = tloc0 + row + tap - (KWIN >> 1);
            const bool valid = (KWIN == 1) || (src >= 0 && src < Tb);
            const size_t go = (size_t)(gseg + (valid ? src : 0))*256 + cb + kc*8;
            const uint32_t d = swst(row, kc);
            cpa16(sb + st*T3     + d, Ahi + go, valid ? 16 : 0);
            cpa16(sb + (3+st)*T3 + d, Alo + go, valid ? 16 : 0);
        }
        #pragma unroll
        for (int h2 = 0; h2 < 4; h2++) {
            const int c = tid + h2*128;
            const int row = c >> 2, kc = c & 3;
            const size_t go = (size_t)(n0 + row)*K + s*32 + kc*8;
            const uint32_t d = swst(row, kc);
            cpa16(sb + (6+st)*T3 + d, Whi + go, 16);
            cpa16(sb + (9+st)*T3 + d, Wlo + go, 16);
        }
        asm volatile("cp.async.commit_group;");
    };

    auto compute_stage = [&](int st) {
        const uint32_t aHi = sb + st*T3,     aLo = sb + (3+st)*T3;
        const uint32_t bHi = sb + (6+st)*T3, bLo = sb + (9+st)*T3;
        #pragma unroll
        for (int q = 0; q < 2; q++) {
            uint32_t ah[4][4], al[4][4], bh[4][4], bl[4][4];
            #pragma unroll
            for (int mt = 0; mt < 4; mt++) {
                const uint32_t oA = (uint32_t)(rowA[mt]*64 + (((2*q + hA) ^ swA[mt]) << 4));
                ldm4(ah[mt], aHi + oA);
                ldm4(al[mt], aLo + oA);
            }
            #pragma unroll
            for (int p = 0; p < 4; p++) {
                const uint32_t oB = (uint32_t)(rowB[p]*64 + (((2*q + hB) ^ swB[p]) << 4));
                ldm4(bh[p], bHi + oB);
                ldm4(bl[p], bLo + oB);
            }
            #pragma unroll
            for (int mt = 0; mt < 4; mt++)
                #pragma unroll
                for (int p = 0; p < 4; p++) {
                    mma16816(acc[mt][2*p],   ah[mt], bh[p][0], bh[p][1]);
                    mma16816(acc[mt][2*p+1], ah[mt], bh[p][2], bh[p][3]);
                }
            #pragma unroll
            for (int mt = 0; mt < 4; mt++)
                #pragma unroll
                for (int p = 0; p < 4; p++) {
                    mma16816(acc[mt][2*p],   al[mt], bh[p][0], bh[p][1]);
                    mma16816(acc[mt][2*p+1], al[mt], bh[p][2], bh[p][3]);
                }
            #pragma unroll
            for (int mt = 0; mt < 4; mt++)
                #pragma unroll
                for (int p = 0; p < 4; p++) {
                    mma16816(acc[mt][2*p],   ah[mt], bl[p][0], bl[p][1]);
                    mma16816(acc[mt][2*p+1], ah[mt], bl[p][2], bl[p][3]);
                }
        }
    };

    if (!zerotile) {
        load_stage(0, 0);
        load_stage(1, 1);
        int stc = 0, stl = 2;
        #pragma unroll 1
        for (int s = 0; s < NS; s++) {
            if (s + 1 < NS) { asm volatile("cp.async.wait_group 1;"); }
            else            { asm volatile("cp.async.wait_group 0;"); }
            __syncthreads();
            if (s + 2 < NS) load_stage(s + 2, stl);
            compute_stage(stc);
            stc = (stc == 2) ? 0 : stc + 1;
            stl = (stl == 2) ? 0 : stl + 1;
        }
    }

    #pragma unroll
    for (int mt = 0; mt < 4; mt++) {
        const int r = row0 + wm*64 + mt*16 + (lid >> 2);
        const bool m0 = MASK && ((r     & tmask) >= mlv);
        const bool m1 = MASK && (((r+8) & tmask) >= mlv);
        #pragma unroll
        for (int nt = 0; nt < 8; nt++) {
            const int c = n0 + wn*64 + nt*8 + (lid & 3)*2;
            const float bb0 = bias[c], bb1 = bias[c+1];
            float v0 = acc[mt][nt][0] + bb0, v1 = acc[mt][nt][1] + bb1;
            float v2 = acc[mt][nt][2] + bb0, v3 = acc[mt][nt][3] + bb1;
            if (RELU) { v0 = fmaxf(v0,0.f); v1 = fmaxf(v1,0.f); v2 = fmaxf(v2,0.f); v3 = fmaxf(v3,0.f); }
            if (m0) { v0 = 0.f; v1 = 0.f; }
            if (m1) { v2 = 0.f; v3 = 0.f; }
            *(float2*)(Y + (size_t)r*Cout + c)     = make_float2(v0, v1);
            *(float2*)(Y + (size_t)(r+8)*Cout + c) = make_float2(v2, v3);
        }
    }
}

// ---------------- GEMM kernels ---------------------------------------------------
__global__ __launch_bounds__(128, 2)
void gemm_dual(const bf16* Ah0, const bf16* Al0, const bf16* Wh0, const bf16* Wl0,
               const float* b0, float* Y0, int tm0, int skip0,
               const bf16* Ah1, const bf16* Al1, const bf16* Wh1, const bf16* Wl1,
               const float* b1, float* Y1, int tm1,
               const int* mellen, int PB) {
    extern __shared__ char smc[];
    const uint32_t sb = (uint32_t)__cvta_generic_to_shared(smc);
    const int bx = blockIdx.x;
    const int n0 = blockIdx.y * 128;
    if (bx < PB) {
        gemm_core<3,true,false>(Ah0, Al0, Wh0, Wl0, b0, Y0, 256, bx*128, n0, tm0,
                                mellen, skip0, sb);
    } else {
        gemm_core<3,true,false>(Ah1, Al1, Wh1, Wl1, b1, Y1, 256, (bx-PB)*128, n0, tm1,
                                nullptr, 0, sb);
    }
}

__global__ __launch_bounds__(128, 2)
void gemm_proj(const bf16* Ah, const bf16* Al, const bf16* Wh, const bf16* Wl,
               const float* b, float* Y, const int* mellen) {
    extern __shared__ char smc[];
    const uint32_t sb = (uint32_t)__cvta_generic_to_shared(smc);
    gemm_core<1,false,true>(Ah, Al, Wh, Wl, b, Y, 512,
                            blockIdx.x*128, blockIdx.y*128, 2047, mellen, 0, sb);
}

// ---------------- weight prep + length regulator (merged) -------------------------
__global__ void prep_len(const float* __restrict__ dp_w1, const float* __restrict__ dp_w2,
                         const float* __restrict__ pp_w1, const float* __restrict__ pp_w2,
                         const float* __restrict__ proj_w,
                         bf16* __restrict__ H, bf16* __restrict__ L,
                         const int* __restrict__ dur, int* __restrict__ idxb,
                         int* __restrict__ mellen, float* __restrict__ out_mel) {
    int bid = blockIdx.x;
    if (bid < 3072) {
        int slot = bid / 768;
        const float* W = (slot == 0) ? dp_w1 : (slot == 1) ? dp_w2 : (slot == 2) ? pp_w1 : pp_w2;
        int o = (bid - slot*768) * 256 + threadIdx.x;
        int f = o / 768;
        int r = o - f * 768;
        int tap = r >> 8;
        int c = r & 255;
        float w = W[f*768 + c*3 + tap];
        bf16 h, l; split1(w, h, l);
        H[slot*WCONV + o] = h; L[slot*WCONV + o] = l;
    } else if (bid < 3584) {
        int o = (bid - 3072) * 256 + threadIdx.x;
        int n = o >> 8;
        int k = o & 255;
        float w = proj_w[k*512 + n];
        bf16 h, l; split1(w, h, l);
        H[4*WCONV + o] = h; L[4*WCONV + o] = l;
    } else {
        __shared__ int cum[TSLEN];
        int b = bid - 3584;
        int t = threadIdx.x;
        cum[t] = dur[b*TSLEN + t];
        __syncthreads();
        for (int off = 1; off < TSLEN; off <<= 1) {
            int v = (t >= off) ? cum[t - off] : 0;
            __syncthreads();
            cum[t] += v;
            __syncthreads();
        }
        int ml = min(cum[TSLEN-1], MAXMEL);
        if (t == 0) { mellen[b] = ml; out_mel[b] = (float)ml; }
        for (int m = t; m < MAXMEL; m += TSLEN) {
            int lo = 0, hi = TSLEN;
            while (lo < hi) { int mid = (lo + hi) >> 1; if (cum[mid] <= m) lo = mid + 1; else hi = mid; }
            idxb[b*MAXMEL + m] = min(lo, TSLEN - 1);
        }
    }
}

// ---------------- gather (pitch) + split (duration) — R14 form --------------------
__global__ __launch_bounds__(256)
void gather_split(const float* __restrict__ ling, const int* __restrict__ idxb,
                  const int* __restrict__ mellen,
                  bf16* __restrict__ dh, bf16* __restrict__ dl) {
    int bx = blockIdx.x;
    const int lane = threadIdx.x & 31;
    const int c0 = lane*8;
    if (bx < PROWS/8) {
        int row = bx*8 + (threadIdx.x >> 5);
        int b = row >> 11;
        int m = row & (MAXMEL - 1);
        bool masked = (m >= mellen[b]);
        int src = idxb[row];
        float y[8] = {0,0,0,0,0,0,0,0};
        if (!masked) ld8(ling + ((size_t)b*TSLEN + src)*DD + c0, y);
        uint4 hv, lv;
        split8(y, hv, lv);
        *(uint4*)(g_xh + (size_t)row*DD + c0) = hv;
        *(uint4*)(g_xl + (size_t)row*DD + c0) = lv;
    } else {
        int row = (bx - PROWS/8)*8 + (threadIdx.x >> 5);
        float y[8];
        ld8(ling + (size_t)row*DD + c0, y);
        uint4 hv, lv;
        split8(y, hv, lv);
        *(uint4*)(dh + (size_t)row*DD + c0) = hv;
        *(uint4*)(dl + (size_t)row*DD + c0) = lv;
    }
}

// ---------------- LayerNorm + split — R14 form (no skip) --------------------------
__global__ __launch_bounds__(256)
void ln_dual(const float* __restrict__ H0, const float* __restrict__ g0,
             const float* __restrict__ be0, bf16* __restrict__ hi0, bf16* __restrict__ lo0,
             int R0,
             const float* __restrict__ H1, const float* __restrict__ g1,
             const float* __restrict__ be1, bf16* __restrict__ hi1, bf16* __restrict__ lo1) {
    const int gr = blockIdx.x*8 + (threadIdx.x >> 5);
    const int lane = threadIdx.x & 31;
    const float *H, *g, *be;
    bf16 *hi, *lo;
    int row;
    if (gr < R0) { H = H0; g = g0; be = be0; hi = hi0; lo = lo0; row = gr; }
    else         { H = H1; g = g1; be = be1; hi = hi1; lo = lo1; row = gr - R0; }
    const int c0 = lane*8;
    float x[8], gg[8], bb[8];
    ld8(H + (size_t)row*FF + c0, x);
    ld8(g + c0, gg);
    ld8(be + c0, bb);
    float s1 = 0.f, s2 = 0.f;
    #pragma unroll
    for (int i = 0; i < 8; i++) { s1 += x[i]; s2 += x[i]*x[i]; }
    s1 = wredsum(s1);
    s2 = wredsum(s2);
    float mean = s1 * (1.f/256.f);
    float var  = s2 * (1.f/256.f) - mean*mean;
    float rstd = rsqrtf(var + 1e-5f);
    float y[8];
    #pragma unroll
    for (int i = 0; i < 8; i++)
        y[i] = (x[i] - mean) * rstd * gg[i] + bb[i];
    uint4 hv, lv;
    split8(y, hv, lv);
    *(uint4*)(hi + (size_t)row*FF + c0) = hv;
    *(uint4*)(lo + (size_t)row*FF + c0) = lv;
}

// ---------------- heads: warp per row, masked-row early out ------------------------
__global__ __launch_bounds__(256)
void heads_dual(const float* __restrict__ Hp, const float* __restrict__ gp,
                const float* __restrict__ bep, const float* __restrict__ lwp,
                const float* __restrict__ lbp, const float* __restrict__ bins,
                const float* __restrict__ emb, const int* __restrict__ mellen,
                const float* __restrict__ ling, const int* __restrict__ idxb,
                float* __restrict__ pout,
                const float* __restrict__ Hd, const float* __restrict__ gd,
                const float* __restrict__ bed, const float* __restrict__ lwd,
                const float* __restrict__ lbd, float* __restrict__ dout) {
    const int gr = blockIdx.x*8 + (threadIdx.x >> 5);
    const int lane = threadIdx.x & 31;
    const bool isPitch = (gr < PROWS);
    const int row = isPitch ? gr : gr - PROWS;

    if (isPitch) {
        const int b = row >> 11;
        const int m = row & (MAXMEL - 1);
        if (m >= mellen[b]) {                  // masked: pout=0, nothing else needed
            if (lane == 0) pout[row] = 0.f;
            return;
        }
    }

    const float* H  = isPitch ? Hp  : Hd;
    const float* g  = isPitch ? gp  : gd;
    const float* be = isPitch ? bep : bed;
    const float* lw = isPitch ? lwp : lwd;
    const float* lb = isPitch ? lbp : lbd;

    const int c0 = lane*8;
    float x[8], gg[8], bb[8], ww[8];
    ld8(H + (size_t)row*FF + c0, x);
    ld8(g + c0, gg);
    ld8(be + c0, bb);
    ld8(lw + c0, ww);
    float s1 = 0.f, s2 = 0.f;
    #pragma unroll
    for (int i = 0; i < 8; i++) { s1 += x[i]; s2 += x[i]*x[i]; }
    s1 = wredsum(s1);
    s2 = wredsum(s2);
    float mean = s1 * (1.f/256.f);
    float var  = s2 * (1.f/256.f) - mean*mean;
    float rstd = rsqrtf(var + 1e-5f);
    float dot = 0.f;
    #pragma unroll
    for (int i = 0; i < 8; i++)
        dot += ((x[i] - mean) * rstd * gg[i] + bb[i]) * ww[i];
    dot = wredsum(dot);
    float a = dot + lb[0];

    if (isPitch) {
        const int b = row >> 11;
        if (lane == 0) pout[row] = a;
        int lo = 0, hi = NBINS - 1;
        while (lo < hi) { int mid = (lo + hi) >> 1; if (bins[mid] < a) lo = mid + 1; else hi = mid; }
        const int bkt = lo;
        const int src = idxb[row];
        float ev[8], bv[8];
        ld8(emb + (size_t)bkt*DD + c0, ev);
        ld8(ling + ((size_t)b*TSLEN + src)*DD + c0, bv);
        float xv[8];
        #pragma unroll
        for (int i = 0; i < 8; i++) xv[i] = bv[i] + ev[i];
        uint4 hv, lv;
        split8(xv, hv, lv);
        *(uint4*)(g_xh + (size_t)row*DD + c0) = hv;
        *(uint4*)(g_xl + (size_t)row*DD + c0) = lv;
    } else {
        if (lane == 0) dout[row] = a;
    }
}

// ------------------------------- launch ------------------------------------------
extern "C" void kernel_launch(void* const* d_in, const int* in_sizes, int n_in,
                              void* d_out, int out_size) {
    const float* ling   = (const float*)d_in[0];
    const int*   dur    = (const int*)  d_in[1];
    const float* dp_w1  = (const float*)d_in[3];
    const float* dp_b1  = (const float*)d_in[4];
    const float* dp_g1  = (const float*)d_in[5];
    const float* dp_be1 = (const float*)d_in[6];
    const float* dp_w2  = (const float*)d_in[7];
    const float* dp_b2  = (const float*)d_in[8];
    const float* dp_g2  = (const float*)d_in[9];
    const float* dp_be2 = (const float*)d_in[10];
    const float* dp_lw  = (const float*)d_in[11];
    const float* dp_lb  = (const float*)d_in[12];
    const float* pp_w1  = (const float*)d_in[13];
    const float* pp_b1  = (const float*)d_in[14];
    const float* pp_g1  = (const float*)d_in[15];
    const float* pp_be1 = (const float*)d_in[16];
    const float* pp_w2  = (const float*)d_in[17];
    const float* pp_b2  = (const float*)d_in[18];
    const float* pp_g2  = (const float*)d_in[19];
    const float* pp_be2 = (const float*)d_in[20];
    const float* pp_lw  = (const float*)d_in[21];
    const float* pp_lb  = (const float*)d_in[22];
    const float* bins   = (const float*)d_in[23];
    const float* emb    = (const float*)d_in[24];
    const float* proj_w = (const float*)d_in[25];
    const float* proj_b = (const float*)d_in[26];

    float* out = (float*)d_out;

    float *bufA, *bufB;
    bf16 *wh, *wl, *xh, *xl, *yh, *yl, *dh, *dl;
    int *idxb, *mellen;
    cudaGetSymbolAddress((void**)&bufA,   g_bufA);
    cudaGetSymbolAddress((void**)&bufB,   g_bufB);
    cudaGetSymbolAddress((void**)&wh,     g_wh);
    cudaGetSymbolAddress((void**)&wl,     g_wl);
    cudaGetSymbolAddress((void**)&xh,     g_xh);
    cudaGetSymbolAddress((void**)&xl,     g_xl);
    cudaGetSymbolAddress((void**)&yh,     g_yh);
    cudaGetSymbolAddress((void**)&yl,     g_yl);
    cudaGetSymbolAddress((void**)&dh,     g_dh);
    cudaGetSymbolAddress((void**)&dl,     g_dl);
    cudaGetSymbolAddress((void**)&idxb,   g_idx);
    cudaGetSymbolAddress((void**)&mellen, g_mellen);

    cudaFuncSetAttribute(gemm_dual, cudaFuncAttributeMaxDynamicSharedMemorySize, SM_TOTAL3);
    cudaFuncSetAttribute(gemm_proj, cudaFuncAttributeMaxDynamicSharedMemorySize, SM_TOTAL3);

    // 1: weight prep + length regulator (merged)
    prep_len<<<3584 + BB, 256>>>(dp_w1, dp_w2, pp_w1, pp_w2, proj_w, wh, wl,
                                 dur, idxb, mellen, out + MEL_OFF);
    // 2: gather (pitch) + split (duration)
    gather_split<<<PROWS/8 + DROWS/8, 256>>>(ling, idxb, mellen, dh, dl);
    // 3: conv1 dual (skipmode 1)
    gemm_dual<<<dim3(512 + 64, 2), 128, SM_TOTAL3>>>(
        xh, xl, wh + 2*WCONV, wl + 2*WCONV, pp_b1, bufA, 2047, 1,
        dh, dl, wh + 0*WCONV, wl + 0*WCONV, dp_b1, bufB, 255, mellen, 512);
    // 4: LN dual <- ncu capture slot
    ln_dual<<<(PROWS + DROWS)/8, 256>>>(bufA, pp_g1, pp_be1, yh, yl, PROWS,
                                        bufB, dp_g1, dp_be1, dh, dl);
    // 5: conv2 dual (skipmode 2)
    gemm_dual<<<dim3(512 + 64, 2), 128, SM_TOTAL3>>>(
        yh, yl, wh + 3*WCONV, wl + 3*WCONV, pp_b2, bufA, 2047, 2,
        dh, dl, wh + 1*WCONV, wl + 1*WCONV, dp_b2, bufB, 255, mellen, 512);
    // 6: heads dual (masked-row early out)
    heads_dual<<<(PROWS + DROWS)/8, 256>>>(
        bufA, pp_g2, pp_be2, pp_lw, pp_lb, bins, emb, mellen, ling, idxb, out + PITCH_OFF,
        bufB, dp_g2, dp_be2, dp_lw, dp_lb, out + LOGDUR_OFF);
    // 7: final projection (masked; fully-masked tiles zero-store fast path)
    gemm_proj<<<dim3(512, 4), 128, SM_TOTAL3>>>(
        xh, xl, wh + 4*WCONV, wl + 4*WCONV, proj_b, out, mellen);
}

// round 17
// speedup vs baseline: 1.0513x; 1.0433x over previous
#include <cuda_runtime.h>
#include <cuda_bf16.h>
#include <math.h>
#include <stdint.h>

#define BB      32
#define TSLEN   256
#define DD      256
#define FF      256
#define MAXMEL  2048
#define NBINS   256

#define OUT_ELEMS   (BB*MAXMEL*2*DD)
#define LOGDUR_OFF  OUT_ELEMS
#define PITCH_OFF   (LOGDUR_OFF + BB*TSLEN)
#define MEL_OFF     (PITCH_OFF + BB*MAXMEL)

#define WCONV (256*768)
#define WPROJ (512*256)
#define PROWS (BB*MAXMEL)
#define DROWS (BB*TSLEN)

typedef __nv_bfloat16 bf16;

// ---------------- scratch -------------------------------------------------------
__device__ __align__(128) float g_bufA[PROWS*FF];
__device__ __align__(128) float g_bufB[DROWS*FF];
__device__ __align__(128) bf16  g_xh[PROWS*DD];
__device__ __align__(128) bf16  g_xl[PROWS*DD];
__device__ __align__(128) bf16  g_yh[PROWS*FF];
__device__ __align__(128) bf16  g_yl[PROWS*FF];
__device__ __align__(128) bf16  g_dh[DROWS*DD];
__device__ __align__(128) bf16  g_dl[DROWS*DD];
__device__ __align__(128) bf16  g_wh[4*WCONV + WPROJ];
__device__ __align__(128) bf16  g_wl[4*WCONV + WPROJ];
__device__ int g_idx[PROWS];
__device__ int g_mellen[BB];

// ---------------- helpers -------------------------------------------------------
__device__ __forceinline__ void cpa16(uint32_t d, const void* s, int sz) {
    asm volatile("cp.async.cg.shared.global [%0], [%1], 16, %2;" :: "r"(d), "l"(s), "r"(sz));
}
__device__ __forceinline__ void ldm4(uint32_t* r, uint32_t a) {
    asm volatile("ldmatrix.sync.aligned.m8n8.x4.shared.b16 {%0,%1,%2,%3}, [%4];"
        : "=r"(r[0]), "=r"(r[1]), "=r"(r[2]), "=r"(r[3]) : "r"(a));
}
__device__ __forceinline__ void mma16816(float* c, const uint32_t* a, uint32_t b0, uint32_t b1) {
    asm volatile(
        "mma.sync.aligned.m16n8k16.row.col.f32.bf16.bf16.f32 "
        "{%0,%1,%2,%3}, {%4,%5,%6,%7}, {%8,%9}, {%0,%1,%2,%3};"
        : "+f"(c[0]), "+f"(c[1]), "+f"(c[2]), "+f"(c[3])
        : "r"(a[0]), "r"(a[1]), "r"(a[2]), "r"(a[3]), "r"(b0), "r"(b1));
}
__device__ __forceinline__ void split1(float x, bf16& h, bf16& l) {
    h = __float2bfloat16_rn(x);
    l = __float2bfloat16_rn(x - __bfloat162float(h));
}
__device__ __forceinline__ float wredsum(float v) {
    #pragma unroll
    for (int o = 16; o; o >>= 1) v += __shfl_xor_sync(0xffffffffu, v, o);
    return v;
}
__device__ __forceinline__ void split8(const float* y, uint4& hv, uint4& lv) {
    uint32_t* hp = (uint32_t*)&hv;
    uint32_t* lp = (uint32_t*)&lv;
    #pragma unroll
    for (int i = 0; i < 4; i++) {
        bf16 h0, l0, h1, l1;
        split1(y[2*i],   h0, l0);
        split1(y[2*i+1], h1, l1);
        hp[i] = (uint32_t)__bfloat16_as_ushort(h0) | ((uint32_t)__bfloat16_as_ushort(h1) << 16);
        lp[i] = (uint32_t)__bfloat16_as_ushort(l0) | ((uint32_t)__bfloat16_as_ushort(l1) << 16);
    }
}
__device__ __forceinline__ void ld8(const float* p, float* y) {
    float4 a = *(const float4*)(p);
    float4 b = *(const float4*)(p + 4);
    y[0]=a.x; y[1]=a.y; y[2]=a.z; y[3]=a.w; y[4]=b.x; y[5]=b.y; y[6]=b.z; y[7]=b.w;
}

// 3-stage swizzled SMEM
#define T3 8192
#define SM_TOTAL3 (12*T3)
__device__ __forceinline__ uint32_t swst(int row, int kc) {
    return (uint32_t)(row*64 + ((kc ^ ((row>>1)&3)) << 4));
}

// ---------------- GEMM core: interleaved LDSM/MMA compute stage --------------------
template<int KWIN, bool RELU, bool MASK>
__device__ __forceinline__ void gemm_core(
    const bf16* __restrict__ Ahi, const bf16* __restrict__ Alo,
    const bf16* __restrict__ Whi, const bf16* __restrict__ Wlo,
    const float* __restrict__ bias, float* __restrict__ Y, int Cout,
    int row0, int n0, int tmask, const int* __restrict__ mellen,
    int skipmode, uint32_t sb)
{
    constexpr int NS = KWIN * 8;
    constexpr int K  = KWIN * 256;
    const int tid = threadIdx.x;
    const int wid = tid >> 5, lid = tid & 31;
    const int wm = wid >> 1, wn = wid & 1;
    const int tloc0 = row0 & tmask;
    const int gseg  = row0 - tloc0;
    const int Tb    = tmask + 1;

    int mlv = 0;
    if (MASK || skipmode) mlv = mellen[(uint32_t)row0 / (uint32_t)Tb];
    if (skipmode == 1 && tloc0 > mlv)  return;
    if (skipmode == 2 && tloc0 >= mlv) return;
    const bool zerotile = MASK && (tloc0 >= mlv);

    int rowA[4], swA[4];
    #pragma unroll
    for (int mt = 0; mt < 4; mt++) {
        rowA[mt] = wm*64 + mt*16 + (lid & 15);
        swA[mt]  = (rowA[mt] >> 1) & 3;
    }
    const int hA = (lid >> 4) & 1;
    int rowB[4], swB[4];
    #pragma unroll
    for (int p = 0; p < 4; p++) {
        rowB[p] = wn*64 + p*16 + (lid & 7) + ((lid & 16) >> 1);
        swB[p]  = (rowB[p] >> 1) & 3;
    }
    const int hB = (lid >> 3) & 1;

    float acc[4][8][4];
    #pragma unroll
    for (int i = 0; i < 4; i++)
        #pragma unroll
        for (int j = 0; j < 8; j++)
            #pragma unroll
            for (int e = 0; e < 4; e++) acc[i][j][e] = 0.f;

    auto load_stage = [&](int s, int st) {
        const int tap = (KWIN == 3) ? (s >> 3) : 0;
        const int cb  = (s & 7) * 32;
        #pragma unroll
        for (int h2 = 0; h2 < 4; h2++) {
            const int c = tid + h2*128;
            const int row = c >> 2, kc = c & 3;
            const int src = tloc0 + row + tap - (KWIN >> 1);
            const bool valid = (KWIN == 1) || (src >= 0 && src < Tb);
            const size_t go = (size_t)(gseg + (valid ? src : 0))*256 + cb + kc*8;
            const uint32_t d = swst(row, kc);
            cpa16(sb + st*T3     + d, Ahi + go, valid ? 16 : 0);
            cpa16(sb + (3+st)*T3 + d, Alo + go, valid ? 16 : 0);
        }
        #pragma unroll
        for (int h2 = 0; h2 < 4; h2++) {
            const int c = tid + h2*128;
            const int row = c >> 2, kc = c & 3;
            const size_t go = (size_t)(n0 + row)*K + s*32 + kc*8;
            const uint32_t d = swst(row, kc);
            cpa16(sb + (6+st)*T3 + d, Whi + go, 16);
            cpa16(sb + (9+st)*T3 + d, Wlo + go, 16);
        }
        asm volatile("cp.async.commit_group;");
    };

    auto compute_stage = [&](int st) {
        const uint32_t aHi = sb + st*T3,     aLo = sb + (3+st)*T3;
        const uint32_t bHi = sb + (6+st)*T3, bLo = sb + (9+st)*T3;
        #pragma unroll
        for (int q = 0; q < 2; q++) {
            uint32_t ah[4][4], al[4][4];
            #pragma unroll
            for (int mt = 0; mt < 4; mt++) {
                const uint32_t oA = (uint32_t)(rowA[mt]*64 + (((2*q + hA) ^ swA[mt]) << 4));
                ldm4(ah[mt], aHi + oA);
                ldm4(al[mt], aLo + oA);
            }
            // per B-tile: 2 LDSM then 24 MMAs (per-acc term order unchanged)
            #pragma unroll
            for (int p = 0; p < 4; p++) {
                uint32_t bh[4], bl[4];
                const uint32_t oB = (uint32_t)(rowB[p]*64 + (((2*q + hB) ^ swB[p]) << 4));
                ldm4(bh, bHi + oB);
                ldm4(bl, bLo + oB);
                #pragma unroll
                for (int mt = 0; mt < 4; mt++) {
                    mma16816(acc[mt][2*p],   ah[mt], bh[0], bh[1]);
                    mma16816(acc[mt][2*p+1], ah[mt], bh[2], bh[3]);
                }
                #pragma unroll
                for (int mt = 0; mt < 4; mt++) {
                    mma16816(acc[mt][2*p],   al[mt], bh[0], bh[1]);
                    mma16816(acc[mt][2*p+1], al[mt], bh[2], bh[3]);
                }
                #pragma unroll
                for (int mt = 0; mt < 4; mt++) {
                    mma16816(acc[mt][2*p],   ah[mt], bl[0], bl[1]);
                    mma16816(acc[mt][2*p+1], ah[mt], bl[2], bl[3]);
                }
            }
        }
    };

    if (!zerotile) {
        load_stage(0, 0);
        load_stage(1, 1);
        int stc = 0, stl = 2;
        #pragma unroll 1
        for (int s = 0; s < NS; s++) {
            if (s + 1 < NS) { asm volatile("cp.async.wait_group 1;"); }
            else            { asm volatile("cp.async.wait_group 0;"); }
            __syncthreads();
            if (s + 2 < NS) load_stage(s + 2, stl);
            compute_stage(stc);
            stc = (stc == 2) ? 0 : stc + 1;
            stl = (stl == 2) ? 0 : stl + 1;
        }
    }

    #pragma unroll
    for (int mt = 0; mt < 4; mt++) {
        const int r = row0 + wm*64 + mt*16 + (lid >> 2);
        const bool m0 = MASK && ((r     & tmask) >= mlv);
        const bool m1 = MASK && (((r+8) & tmask) >= mlv);
        #pragma unroll
        for (int nt = 0; nt < 8; nt++) {
            const int c = n0 + wn*64 + nt*8 + (lid & 3)*2;
            const float bb0 = bias[c], bb1 = bias[c+1];
            float v0 = acc[mt][nt][0] + bb0, v1 = acc[mt][nt][1] + bb1;
            float v2 = acc[mt][nt][2] + bb0, v3 = acc[mt][nt][3] + bb1;
            if (RELU) { v0 = fmaxf(v0,0.f); v1 = fmaxf(v1,0.f); v2 = fmaxf(v2,0.f); v3 = fmaxf(v3,0.f); }
            if (m0) { v0 = 0.f; v1 = 0.f; }
            if (m1) { v2 = 0.f; v3 = 0.f; }
            *(float2*)(Y + (size_t)r*Cout + c)     = make_float2(v0, v1);
            *(float2*)(Y + (size_t)(r+8)*Cout + c) = make_float2(v2, v3);
        }
    }
}

// ---------------- GEMM kernels ---------------------------------------------------
__global__ __launch_bounds__(128, 2)
void gemm_dual(const bf16* Ah0, const bf16* Al0, const bf16* Wh0, const bf16* Wl0,
               const float* b0, float* Y0, int tm0, int skip0,
               const bf16* Ah1, const bf16* Al1, const bf16* Wh1, const bf16* Wl1,
               const float* b1, float* Y1, int tm1,
               const int* mellen, int PB) {
    extern __shared__ char smc[];
    const uint32_t sb = (uint32_t)__cvta_generic_to_shared(smc);
    const int bx = blockIdx.x;
    const int n0 = blockIdx.y * 128;
    if (bx < PB) {
        gemm_core<3,true,false>(Ah0, Al0, Wh0, Wl0, b0, Y0, 256, bx*128, n0, tm0,
                                mellen, skip0, sb);
    } else {
        gemm_core<3,true,false>(Ah1, Al1, Wh1, Wl1, b1, Y1, 256, (bx-PB)*128, n0, tm1,
                                nullptr, 0, sb);
    }
}

__global__ __launch_bounds__(128, 2)
void gemm_proj(const bf16* Ah, const bf16* Al, const bf16* Wh, const bf16* Wl,
               const float* b, float* Y, const int* mellen) {
    extern __shared__ char smc[];
    const uint32_t sb = (uint32_t)__cvta_generic_to_shared(smc);
    gemm_core<1,false,true>(Ah, Al, Wh, Wl, b, Y, 512,
                            blockIdx.x*128, blockIdx.y*128, 2047, mellen, 0, sb);
}

// ---------------- weight prep + length regulator (merged) -------------------------
__global__ void prep_len(const float* __restrict__ dp_w1, const float* __restrict__ dp_w2,
                         const float* __restrict__ pp_w1, const float* __restrict__ pp_w2,
                         const float* __restrict__ proj_w,
                         bf16* __restrict__ H, bf16* __restrict__ L,
                         const int* __restrict__ dur, int* __restrict__ idxb,
                         int* __restrict__ mellen, float* __restrict__ out_mel) {
    int bid = blockIdx.x;
    if (bid < 3072) {
        int slot = bid / 768;
        const float* W = (slot == 0) ? dp_w1 : (slot == 1) ? dp_w2 : (slot == 2) ? pp_w1 : pp_w2;
        int o = (bid - slot*768) * 256 + threadIdx.x;
        int f = o / 768;
        int r = o - f * 768;
        int tap = r >> 8;
        int c = r & 255;
        float w = W[f*768 + c*3 + tap];
        bf16 h, l; split1(w, h, l);
        H[slot*WCONV + o] = h; L[slot*WCONV + o] = l;
    } else if (bid < 3584) {
        int o = (bid - 3072) * 256 + threadIdx.x;
        int n = o >> 8;
        int k = o & 255;
        float w = proj_w[k*512 + n];
        bf16 h, l; split1(w, h, l);
        H[4*WCONV + o] = h; L[4*WCONV + o] = l;
    } else {
        __shared__ int cum[TSLEN];
        int b = bid - 3584;
        int t = threadIdx.x;
        cum[t] = dur[b*TSLEN + t];
        __syncthreads();
        for (int off = 1; off < TSLEN; off <<= 1) {
            int v = (t >= off) ? cum[t - off] : 0;
            __syncthreads();
            cum[t] += v;
            __syncthreads();
        }
        int ml = min(cum[TSLEN-1], MAXMEL);
        if (t == 0) { mellen[b] = ml; out_mel[b] = (float)ml; }
        for (int m = t; m < MAXMEL; m += TSLEN) {
            int lo = 0, hi = TSLEN;
            while (lo < hi) { int mid = (lo + hi) >> 1; if (cum[mid] <= m) lo = mid + 1; else hi = mid; }
            idxb[b*MAXMEL + m] = min(lo, TSLEN - 1);
        }
    }
}

// ---------------- gather (pitch) + split (duration) -------------------------------
__global__ __launch_bounds__(256)
void gather_split(const float* __restrict__ ling, const int* __restrict__ idxb,
                  const int* __restrict__ mellen,
                  bf16* __restrict__ dh, bf16* __restrict__ dl) {
    int bx = blockIdx.x;
    const int lane = threadIdx.x & 31;
    const int c0 = lane*8;
    if (bx < PROWS/8) {
        int row = bx*8 + (threadIdx.x >> 5);
        int b = row >> 11;
        int m = row & (MAXMEL - 1);
        bool masked = (m >= mellen[b]);
        int src = idxb[row];
        float y[8] = {0,0,0,0,0,0,0,0};
        if (!masked) ld8(ling + ((size_t)b*TSLEN + src)*DD + c0, y);
        uint4 hv, lv;
        split8(y, hv, lv);
        *(uint4*)(g_xh + (size_t)row*DD + c0) = hv;
        *(uint4*)(g_xl + (size_t)row*DD + c0) = lv;
    } else {
        int row = (bx - PROWS/8)*8 + (threadIdx.x >> 5);
        float y[8];
        ld8(ling + (size_t)row*DD + c0, y);
        uint4 hv, lv;
        split8(y, hv, lv);
        *(uint4*)(dh + (size_t)row*DD + c0) = hv;
        *(uint4*)(dl + (size_t)row*DD + c0) = lv;
    }
}

// ---------------- LayerNorm + split: warp per row ----------------------------------
__global__ __launch_bounds__(256)
void ln_dual(const float* __restrict__ H0, const float* __restrict__ g0,
             const float* __restrict__ be0, bf16* __restrict__ hi0, bf16* __restrict__ lo0,
             int R0,
             const float* __restrict__ H1, const float* __restrict__ g1,
             const float* __restrict__ be1, bf16* __restrict__ hi1, bf16* __restrict__ lo1) {
    const int gr = blockIdx.x*8 + (threadIdx.x >> 5);
    const int lane = threadIdx.x & 31;
    const float *H, *g, *be;
    bf16 *hi, *lo;
    int row;
    if (gr < R0) { H = H0; g = g0; be = be0; hi = hi0; lo = lo0; row = gr; }
    else         { H = H1; g = g1; be = be1; hi = hi1; lo = lo1; row = gr - R0; }
    const int c0 = lane*8;
    float x[8], gg[8], bb[8];
    ld8(H + (size_t)row*FF + c0, x);
    ld8(g + c0, gg);
    ld8(be + c0, bb);
    float s1 = 0.f, s2 = 0.f;
    #pragma unroll
    for (int i = 0; i < 8; i++) { s1 += x[i]; s2 += x[i]*x[i]; }
    s1 = wredsum(s1);
    s2 = wredsum(s2);
    float mean = s1 * (1.f/256.f);
    float var  = s2 * (1.f/256.f) - mean*mean;
    float rstd = rsqrtf(var + 1e-5f);
    float y[8];
    #pragma unroll
    for (int i = 0; i < 8; i++)
        y[i] = (x[i] - mean) * rstd * gg[i] + bb[i];
    uint4 hv, lv;
    split8(y, hv, lv);
    *(uint4*)(hi + (size_t)row*FF + c0) = hv;
    *(uint4*)(lo + (size_t)row*FF + c0) = lv;
}

// ---------------- heads: warp per row, masked-row early out ------------------------
__global__ __launch_bounds__(256)
void heads_dual(const float* __restrict__ Hp, const float* __restrict__ gp,
                const float* __restrict__ bep, const float* __restrict__ lwp,
                const float* __restrict__ lbp, const float* __restrict__ bins,
                const float* __restrict__ emb, const int* __restrict__ mellen,
                const float* __restrict__ ling, const int* __restrict__ idxb,
                float* __restrict__ pout,
                const float* __restrict__ Hd, const float* __restrict__ gd,
                const float* __restrict__ bed, const float* __restrict__ lwd,
                const float* __restrict__ lbd, float* __restrict__ dout) {
    const int gr = blockIdx.x*8 + (threadIdx.x >> 5);
    const int lane = threadIdx.x & 31;
    const bool isPitch = (gr < PROWS);
    const int row = isPitch ? gr : gr - PROWS;

    if (isPitch) {
        const int b = row >> 11;
        const int m = row & (MAXMEL - 1);
        if (m >= mellen[b]) {
            if (lane == 0) pout[row] = 0.f;
            return;
        }
    }

    const float* H  = isPitch ? Hp  : Hd;
    const float* g  = isPitch ? gp  : gd;
    const float* be = isPitch ? bep : bed;
    const float* lw = isPitch ? lwp : lwd;
    const float* lb = isPitch ? lbp : lbd;

    const int c0 = lane*8;
    float x[8], gg[8], bb[8], ww[8];
    ld8(H + (size_t)row*FF + c0, x);
    ld8(g + c0, gg);
    ld8(be + c0, bb);
    ld8(lw + c0, ww);
    float s1 = 0.f, s2 = 0.f;
    #pragma unroll
    for (int i = 0; i < 8; i++) { s1 += x[i]; s2 += x[i]*x[i]; }
    s1 = wredsum(s1);
    s2 = wredsum(s2);
    float mean = s1 * (1.f/256.f);
    float var  = s2 * (1.f/256.f) - mean*mean;
    float rstd = rsqrtf(var + 1e-5f);
    float dot = 0.f;
    #pragma unroll
    for (int i = 0; i < 8; i++)
        dot += ((x[i] - mean) * rstd * gg[i] + bb[i]) * ww[i];
    dot = wredsum(dot);
    float a = dot + lb[0];

    if (isPitch) {
        const int b = row >> 11;
        if (lane == 0) pout[row] = a;
        int lo = 0, hi = NBINS - 1;
        while (lo < hi) { int mid = (lo + hi) >> 1; if (bins[mid] < a) lo = mid + 1; else hi = mid; }
        const int bkt = lo;
        const int src = idxb[row];
        float ev[8], bv[8];
        ld8(emb + (size_t)bkt*DD + c0, ev);
        ld8(ling + ((size_t)b*TSLEN + src)*DD + c0, bv);
        float xv[8];
        #pragma unroll
        for (int i = 0; i < 8; i++) xv[i] = bv[i] + ev[i];
        uint4 hv, lv;
        split8(xv, hv, lv);
        *(uint4*)(g_xh + (size_t)row*DD + c0) = hv;
        *(uint4*)(g_xl + (size_t)row*DD + c0) = lv;
    } else {
        if (lane == 0) dout[row] = a;
    }
}

// ------------------------------- launch ------------------------------------------
extern "C" void kernel_launch(void* const* d_in, const int* in_sizes, int n_in,
                              void* d_out, int out_size) {
    const float* ling   = (const float*)d_in[0];
    const int*   dur    = (const int*)  d_in[1];
    const float* dp_w1  = (const float*)d_in[3];
    const float* dp_b1  = (const float*)d_in[4];
    const float* dp_g1  = (const float*)d_in[5];
    const float* dp_be1 = (const float*)d_in[6];
    const float* dp_w2  = (const float*)d_in[7];
    const float* dp_b2  = (const float*)d_in[8];
    const float* dp_g2  = (const float*)d_in[9];
    const float* dp_be2 = (const float*)d_in[10];
    const float* dp_lw  = (const float*)d_in[11];
    const float* dp_lb  = (const float*)d_in[12];
    const float* pp_w1  = (const float*)d_in[13];
    const float* pp_b1  = (const float*)d_in[14];
    const float* pp_g1  = (const float*)d_in[15];
    const float* pp_be1 = (const float*)d_in[16];
    const float* pp_w2  = (const float*)d_in[17];
    const float* pp_b2  = (const float*)d_in[18];
    const float* pp_g2  = (const float*)d_in[19];
    const float* pp_be2 = (const float*)d_in[20];
    const float* pp_lw  = (const float*)d_in[21];
    const float* pp_lb  = (const float*)d_in[22];
    const float* bins   = (const float*)d_in[23];
    const float* emb    = (const float*)d_in[24];
    const float* proj_w = (const float*)d_in[25];
    const float* proj_b = (const float*)d_in[26];

    float* out = (float*)d_out;

    float *bufA, *bufB;
    bf16 *wh, *wl, *xh, *xl, *yh, *yl, *dh, *dl;
    int *idxb, *mellen;
    cudaGetSymbolAddress((void**)&bufA,   g_bufA);
    cudaGetSymbolAddress((void**)&bufB,   g_bufB);
    cudaGetSymbolAddress((void**)&wh,     g_wh);
    cudaGetSymbolAddress((void**)&wl,     g_wl);
    cudaGetSymbolAddress((void**)&xh,     g_xh);
    cudaGetSymbolAddress((void**)&xl,     g_xl);
    cudaGetSymbolAddress((void**)&yh,     g_yh);
    cudaGetSymbolAddress((void**)&yl,     g_yl);
    cudaGetSymbolAddress((void**)&dh,     g_dh);
    cudaGetSymbolAddress((void**)&dl,     g_dl);
    cudaGetSymbolAddress((void**)&idxb,   g_idx);
    cudaGetSymbolAddress((void**)&mellen, g_mellen);

    cudaFuncSetAttribute(gemm_dual, cudaFuncAttributeMaxDynamicSharedMemorySize, SM_TOTAL3);
    cudaFuncSetAttribute(gemm_proj, cudaFuncAttributeMaxDynamicSharedMemorySize, SM_TOTAL3);

    // 1: weight prep + length regulator (merged)
    prep_len<<<3584 + BB, 256>>>(dp_w1, dp_w2, pp_w1, pp_w2, proj_w, wh, wl,
                                 dur, idxb, mellen, out + MEL_OFF);
    // 2: gather (pitch) + split (duration)
    gather_split<<<PROWS/8 + DROWS/8, 256>>>(ling, idxb, mellen, dh, dl);
    // 3: conv1 dual (skipmode 1)
    gemm_dual<<<dim3(512 + 64, 2), 128, SM_TOTAL3>>>(
        xh, xl, wh + 2*WCONV, wl + 2*WCONV, pp_b1, bufA, 2047, 1,
        dh, dl, wh + 0*WCONV, wl + 0*WCONV, dp_b1, bufB, 255, mellen, 512);
    // 4: LN dual <- ncu capture slot
    ln_dual<<<(PROWS + DROWS)/8, 256>>>(bufA, pp_g1, pp_be1, yh, yl, PROWS,
                                        bufB, dp_g1, dp_be1, dh, dl);
    // 5: conv2 dual (skipmode 2)
    gemm_dual<<<dim3(512 + 64, 2), 128, SM_TOTAL3>>>(
        yh, yl, wh + 3*WCONV, wl + 3*WCONV, pp_b2, bufA, 2047, 2,
        dh, dl, wh + 1*WCONV, wl + 1*WCONV, dp_b2, bufB, 255, mellen, 512);
    // 6: heads dual (masked-row early out)
    heads_dual<<<(PROWS + DROWS)/8, 256>>>(
        bufA, pp_g2, pp_be2, pp_lw, pp_lb, bins, emb, mellen, ling, idxb, out + PITCH_OFF,
        bufB, dp_g2, dp_be2, dp_lw, dp_lb, out + LOGDUR_OFF);
    // 7: final projection (masked; fully-masked tiles zero-store fast path)
    gemm_proj<<<dim3(512, 4), 128, SM_TOTAL3>>>(
        xh, xl, wh + 4*WCONV, wl + 4*WCONV, proj_b, out, mellen);
}